// round 4
// baseline (speedup 1.0000x reference)
#include <cuda_runtime.h>
#include <math.h>

#define BB 4
#define AA 4096
#define DD 128
#define TOKENS (BB*AA)

// scratch (no cudaMalloc allowed)
__device__ float g_Q[(size_t)TOKENS*DD];
__device__ float g_K[(size_t)TOKENS*DD];
__device__ float g_V[(size_t)TOKENS*DD];
__device__ float g_H[(size_t)TOKENS*DD];

__device__ __forceinline__ float swishf(float x) {
    return x / (1.0f + __expf(-x));
}

// ---------------- QKV projection: [16384,128] @ [128,128] x3 ----------------
__global__ __launch_bounds__(256, 1) void qkv_kernel(
    const float* __restrict__ x,
    const float* __restrict__ Wq,
    const float* __restrict__ Wk,
    const float* __restrict__ Wv)
{
    extern __shared__ float sm[];
    float* xs = sm;            // 128 x 132 (padded)
    float* ws = sm + 128*132;  // 128 x 128
    const int tid = threadIdx.x;
    const int tx = tid & 15, ty = tid >> 4;
    const int tok0 = blockIdx.x * 128;

    for (int i = tid; i < 128*32; i += 256) {
        int r = i >> 5, c = (i & 31) << 2;
        *(float4*)&xs[r*132 + c] = *(const float4*)&x[(size_t)(tok0 + r)*DD + c];
    }

    for (int w = 0; w < 3; w++) {
        const float* W = (w == 0) ? Wq : (w == 1) ? Wk : Wv;
        float* outp = (w == 0) ? g_Q : (w == 1) ? g_K : g_V;
        __syncthreads();
        for (int i = tid; i < 128*32; i += 256) {
            int r = i >> 5, c = (i & 31) << 2;
            *(float4*)&ws[r*128 + c] = *(const float4*)&W[r*DD + c];
        }
        __syncthreads();
        float acc[8][8];
        #pragma unroll
        for (int i = 0; i < 8; i++)
            #pragma unroll
            for (int j = 0; j < 8; j++) acc[i][j] = 0.f;

        for (int kk = 0; kk < 128; kk++) {
            float xv[8], wv[8];
            #pragma unroll
            for (int i = 0; i < 8; i++) xv[i] = xs[(ty*8+i)*132 + kk];
            #pragma unroll
            for (int j = 0; j < 4; j++) {
                wv[j]   = ws[kk*128 + tx*4 + j];
                wv[4+j] = ws[kk*128 + 64 + tx*4 + j];
            }
            #pragma unroll
            for (int i = 0; i < 8; i++)
                #pragma unroll
                for (int j = 0; j < 8; j++) acc[i][j] += xv[i]*wv[j];
        }
        #pragma unroll
        for (int i = 0; i < 8; i++) {
            size_t t = (size_t)(tok0 + ty*8 + i)*DD;
            *(float4*)&outp[t + tx*4]      = make_float4(acc[i][0],acc[i][1],acc[i][2],acc[i][3]);
            *(float4*)&outp[t + 64 + tx*4] = make_float4(acc[i][4],acc[i][5],acc[i][6],acc[i][7]);
        }
    }
}

// ---------------- flash attention w/ additive connectivity bias ----------------
// BM=128 queries per CTA, BN=64 keys per tile. grid (32,4) = 128 CTAs (1 wave).
__global__ __launch_bounds__(256, 1) void attn_kernel(const float* __restrict__ conn)
{
    extern __shared__ float sm[];
    float* Qs = sm;                  // 128*132
    float* Ks = Qs + 128*132;        // 64*132
    float* Vs = Ks + 64*132;         // 64*128
    float* Ps = Vs + 64*128;         // 128*64
    const int b = blockIdx.y;
    const int q0 = blockIdx.x * 128;
    const int tid = threadIdx.x;
    const int tx = tid & 15, ty = tid >> 4;

    const float* Qg = g_Q + (size_t)b*AA*DD;
    const float* Kg = g_K + (size_t)b*AA*DD;
    const float* Vg = g_V + (size_t)b*AA*DD;

    for (int i = tid; i < 128*32; i += 256) {
        int r = i >> 5, c = (i & 31) << 2;
        *(float4*)&Qs[r*132 + c] = *(const float4*)&Qg[(size_t)(q0 + r)*DD + c];
    }

    float m[8], l[8], O[8][8];
    #pragma unroll
    for (int i = 0; i < 8; i++) {
        m[i] = -1e30f; l[i] = 0.f;
        #pragma unroll
        for (int j = 0; j < 8; j++) O[i][j] = 0.f;
    }

    const float inv_scale = 0.08838834764831845f; // 1/sqrt(128)

    for (int k0 = 0; k0 < AA; k0 += 64) {
        __syncthreads();
        for (int i = tid; i < 64*32; i += 256) {
            int r = i >> 5, c = (i & 31) << 2;
            *(float4*)&Ks[r*132 + c] = *(const float4*)&Kg[(size_t)(k0 + r)*DD + c];
            *(float4*)&Vs[r*128 + c] = *(const float4*)&Vg[(size_t)(k0 + r)*DD + c];
        }
        __syncthreads();

        // S[128x64] = Q tile . K tile^T  (rows 8ty+i, cols 4tx+j)
        float S[8][4];
        #pragma unroll
        for (int i = 0; i < 8; i++) { S[i][0]=0.f; S[i][1]=0.f; S[i][2]=0.f; S[i][3]=0.f; }

        for (int kk = 0; kk < 128; kk += 4) {
            float qv[8][4];
            #pragma unroll
            for (int i = 0; i < 8; i++) {
                float4 t = *(const float4*)&Qs[(ty*8+i)*132 + kk];
                qv[i][0]=t.x; qv[i][1]=t.y; qv[i][2]=t.z; qv[i][3]=t.w;
            }
            #pragma unroll
            for (int u = 0; u < 4; u++) {
                float kv[4];
                #pragma unroll
                for (int j = 0; j < 4; j++) kv[j] = Ks[(tx*4+j)*132 + kk + u];
                #pragma unroll
                for (int i = 0; i < 8; i++)
                    #pragma unroll
                    for (int j = 0; j < 4; j++) S[i][j] += qv[i][u]*kv[j];
            }
        }

        // scale + connectivity bias + online softmax
        #pragma unroll
        for (int i = 0; i < 8; i++) {
            float4 cv = *(const float4*)&conn[((size_t)b*AA + (size_t)(q0 + ty*8 + i))*AA + k0 + tx*4];
            float s0 = S[i][0]*inv_scale + cv.x;
            float s1 = S[i][1]*inv_scale + cv.y;
            float s2 = S[i][2]*inv_scale + cv.z;
            float s3 = S[i][3]*inv_scale + cv.w;
            float mx = fmaxf(fmaxf(s0,s1), fmaxf(s2,s3));
            #pragma unroll
            for (int o = 8; o; o >>= 1) mx = fmaxf(mx, __shfl_xor_sync(0xffffffffu, mx, o));
            float mn = fmaxf(m[i], mx);
            float sc = __expf(m[i] - mn);
            float p0 = __expf(s0 - mn), p1 = __expf(s1 - mn);
            float p2 = __expf(s2 - mn), p3 = __expf(s3 - mn);
            *(float4*)&Ps[(ty*8+i)*64 + tx*4] = make_float4(p0,p1,p2,p3);
            float rs = p0+p1+p2+p3;
            #pragma unroll
            for (int o = 8; o; o >>= 1) rs += __shfl_xor_sync(0xffffffffu, rs, o);
            l[i] = l[i]*sc + rs;
            m[i] = mn;
            #pragma unroll
            for (int j = 0; j < 8; j++) O[i][j] *= sc;
        }
        __syncwarp();

        // O += P . V   (O cols: {4tx..4tx+3} and {64+4tx..64+4tx+3})
        for (int kk = 0; kk < 64; kk += 4) {
            float pv[8][4];
            #pragma unroll
            for (int i = 0; i < 8; i++) {
                float4 t = *(const float4*)&Ps[(ty*8+i)*64 + kk];
                pv[i][0]=t.x; pv[i][1]=t.y; pv[i][2]=t.z; pv[i][3]=t.w;
            }
            #pragma unroll
            for (int u = 0; u < 4; u++) {
                float4 v0 = *(const float4*)&Vs[(kk+u)*128 + tx*4];
                float4 v1 = *(const float4*)&Vs[(kk+u)*128 + 64 + tx*4];
                #pragma unroll
                for (int i = 0; i < 8; i++) {
                    O[i][0] += pv[i][u]*v0.x;
                    O[i][1] += pv[i][u]*v0.y;
                    O[i][2] += pv[i][u]*v0.z;
                    O[i][3] += pv[i][u]*v0.w;
                    O[i][4] += pv[i][u]*v1.x;
                    O[i][5] += pv[i][u]*v1.y;
                    O[i][6] += pv[i][u]*v1.z;
                    O[i][7] += pv[i][u]*v1.w;
                }
            }
        }
        __syncwarp();
    }

    float* Hg = g_H + (size_t)b*AA*DD;
    #pragma unroll
    for (int i = 0; i < 8; i++) {
        float inv = 1.0f / l[i];
        size_t base = (size_t)(q0 + ty*8 + i)*DD;
        *(float4*)&Hg[base + tx*4]      = make_float4(O[i][0]*inv, O[i][1]*inv, O[i][2]*inv, O[i][3]*inv);
        *(float4*)&Hg[base + 64 + tx*4] = make_float4(O[i][4]*inv, O[i][5]*inv, O[i][6]*inv, O[i][7]*inv);
    }
}

// ---------------- swish -> W1 -> swish -> W2 -> LayerNorm ----------------
__global__ __launch_bounds__(256, 1) void mlp_kernel(
    const float* __restrict__ W1, const float* __restrict__ b1,
    const float* __restrict__ W2, const float* __restrict__ b2,
    const float* __restrict__ gamma, const float* __restrict__ beta,
    float* __restrict__ out)
{
    extern __shared__ float sm[];
    float* hs  = sm;              // 128*132
    float* hs2 = hs + 128*132;    // 128*132
    float* ws  = hs2 + 128*132;   // 128*128
    const int tid = threadIdx.x;
    const int tx = tid & 15, ty = tid >> 4;
    const int tok0 = blockIdx.x * 128;

    for (int i = tid; i < 128*32; i += 256) {
        int r = i >> 5, c = (i & 31) << 2;
        float4 v = *(const float4*)&g_H[(size_t)(tok0 + r)*DD + c];
        v.x = swishf(v.x); v.y = swishf(v.y); v.z = swishf(v.z); v.w = swishf(v.w);
        *(float4*)&hs[r*132 + c] = v;
        *(float4*)&ws[r*128 + c] = *(const float4*)&W1[r*DD + c];
    }
    __syncthreads();

    float acc[8][8];
    #pragma unroll
    for (int j = 0; j < 4; j++) {
        float bA = b1[tx*4 + j], bB = b1[64 + tx*4 + j];
        #pragma unroll
        for (int i = 0; i < 8; i++) { acc[i][j] = bA; acc[i][4+j] = bB; }
    }
    for (int kk = 0; kk < 128; kk++) {
        float xv[8], wv[8];
        #pragma unroll
        for (int i = 0; i < 8; i++) xv[i] = hs[(ty*8+i)*132 + kk];
        #pragma unroll
        for (int j = 0; j < 4; j++) {
            wv[j]   = ws[kk*128 + tx*4 + j];
            wv[4+j] = ws[kk*128 + 64 + tx*4 + j];
        }
        #pragma unroll
        for (int i = 0; i < 8; i++)
            #pragma unroll
            for (int j = 0; j < 8; j++) acc[i][j] += xv[i]*wv[j];
    }
    __syncthreads();   // everyone done with ws(W1) & hs

    #pragma unroll
    for (int i = 0; i < 8; i++) {
        *(float4*)&hs2[(ty*8+i)*132 + tx*4] =
            make_float4(swishf(acc[i][0]),swishf(acc[i][1]),swishf(acc[i][2]),swishf(acc[i][3]));
        *(float4*)&hs2[(ty*8+i)*132 + 64 + tx*4] =
            make_float4(swishf(acc[i][4]),swishf(acc[i][5]),swishf(acc[i][6]),swishf(acc[i][7]));
    }
    for (int i = tid; i < 128*32; i += 256) {
        int r = i >> 5, c = (i & 31) << 2;
        *(float4*)&ws[r*128 + c] = *(const float4*)&W2[r*DD + c];
    }
    __syncthreads();

    #pragma unroll
    for (int j = 0; j < 4; j++) {
        float bA = b2[tx*4 + j], bB = b2[64 + tx*4 + j];
        #pragma unroll
        for (int i = 0; i < 8; i++) { acc[i][j] = bA; acc[i][4+j] = bB; }
    }
    for (int kk = 0; kk < 128; kk++) {
        float xv[8], wv[8];
        #pragma unroll
        for (int i = 0; i < 8; i++) xv[i] = hs2[(ty*8+i)*132 + kk];
        #pragma unroll
        for (int j = 0; j < 4; j++) {
            wv[j]   = ws[kk*128 + tx*4 + j];
            wv[4+j] = ws[kk*128 + 64 + tx*4 + j];
        }
        #pragma unroll
        for (int i = 0; i < 8; i++)
            #pragma unroll
            for (int j = 0; j < 8; j++) acc[i][j] += xv[i]*wv[j];
    }

    float gm[8], bt[8];
    #pragma unroll
    for (int j = 0; j < 4; j++) {
        gm[j]   = gamma[tx*4+j]; gm[4+j] = gamma[64+tx*4+j];
        bt[j]   = beta[tx*4+j];  bt[4+j] = beta[64+tx*4+j];
    }
    #pragma unroll
    for (int i = 0; i < 8; i++) {
        float s1 = 0.f, s2 = 0.f;
        #pragma unroll
        for (int j = 0; j < 8; j++) { s1 += acc[i][j]; s2 += acc[i][j]*acc[i][j]; }
        #pragma unroll
        for (int o = 8; o; o >>= 1) {
            s1 += __shfl_xor_sync(0xffffffffu, s1, o);
            s2 += __shfl_xor_sync(0xffffffffu, s2, o);
        }
        float mu  = s1 * (1.0f/128.0f);
        float var = s2 * (1.0f/128.0f) - mu*mu;
        float rstd = rsqrtf(var + 1e-5f);
        size_t base = (size_t)(tok0 + ty*8 + i)*DD;
        float4 o0, o1;
        o0.x = (acc[i][0]-mu)*rstd*gm[0] + bt[0];
        o0.y = (acc[i][1]-mu)*rstd*gm[1] + bt[1];
        o0.z = (acc[i][2]-mu)*rstd*gm[2] + bt[2];
        o0.w = (acc[i][3]-mu)*rstd*gm[3] + bt[3];
        o1.x = (acc[i][4]-mu)*rstd*gm[4] + bt[4];
        o1.y = (acc[i][5]-mu)*rstd*gm[5] + bt[5];
        o1.z = (acc[i][6]-mu)*rstd*gm[6] + bt[6];
        o1.w = (acc[i][7]-mu)*rstd*gm[7] + bt[7];
        *(float4*)&out[base + tx*4]      = o0;
        *(float4*)&out[base + 64 + tx*4] = o1;
    }
}

extern "C" void kernel_launch(void* const* d_in, const int* in_sizes, int n_in,
                              void* d_out, int out_size)
{
    const float* x     = (const float*)d_in[0];
    const float* conn  = (const float*)d_in[1];
    const float* Wq    = (const float*)d_in[2];
    const float* Wk    = (const float*)d_in[3];
    const float* Wv    = (const float*)d_in[4];
    const float* W1    = (const float*)d_in[5];
    const float* b1    = (const float*)d_in[6];
    const float* W2    = (const float*)d_in[7];
    const float* b2    = (const float*)d_in[8];
    const float* gamma = (const float*)d_in[9];
    const float* beta  = (const float*)d_in[10];
    float* out = (float*)d_out;

    const size_t smem_qkv  = (size_t)(128*132 + 128*128) * sizeof(float);              // 133120
    const size_t smem_attn = (size_t)(128*132 + 64*132 + 64*128 + 128*64) * sizeof(float); // 166912
    const size_t smem_mlp  = (size_t)(128*132*2 + 128*128) * sizeof(float);            // 200704

    cudaFuncSetAttribute(qkv_kernel,  cudaFuncAttributeMaxDynamicSharedMemorySize, (int)smem_qkv);
    cudaFuncSetAttribute(attn_kernel, cudaFuncAttributeMaxDynamicSharedMemorySize, (int)smem_attn);
    cudaFuncSetAttribute(mlp_kernel,  cudaFuncAttributeMaxDynamicSharedMemorySize, (int)smem_mlp);

    qkv_kernel<<<128, 256, smem_qkv>>>(x, Wq, Wk, Wv);
    attn_kernel<<<dim3(32, 4), 256, smem_attn>>>(conn);
    mlp_kernel<<<128, 256, smem_mlp>>>(W1, b1, W2, b2, gamma, beta, out);
}

// round 5
// speedup vs baseline: 2.7391x; 2.7391x over previous
#include <cuda_runtime.h>
#include <math.h>
#include <stdint.h>

#define BB 4
#define AA 4096
#define DD 128
#define TOKENS (BB*AA)

__device__ float g_Q[(size_t)TOKENS*DD];
__device__ float g_K[(size_t)TOKENS*DD];
__device__ float g_V[(size_t)TOKENS*DD];
__device__ float g_H[(size_t)TOKENS*DD];

__device__ __forceinline__ float swishf(float x) { return x / (1.0f + __expf(-x)); }

__device__ __forceinline__ uint32_t f2tf32(float x) {
    uint32_t u; asm("cvt.rna.tf32.f32 %0, %1;" : "=r"(u) : "f"(x)); return u;
}
__device__ __forceinline__ void mma_tf32(float* c, const uint32_t* a, uint32_t b0, uint32_t b1) {
    asm volatile("mma.sync.aligned.m16n8k8.row.col.f32.tf32.tf32.f32 "
        "{%0,%1,%2,%3}, {%4,%5,%6,%7}, {%8,%9}, {%0,%1,%2,%3};"
        : "+f"(c[0]), "+f"(c[1]), "+f"(c[2]), "+f"(c[3])
        : "r"(a[0]), "r"(a[1]), "r"(a[2]), "r"(a[3]), "r"(b0), "r"(b1));
}
__device__ __forceinline__ void cp16(float* s, const float* g) {
    uint32_t sa = (uint32_t)__cvta_generic_to_shared(s);
    asm volatile("cp.async.cg.shared.global [%0], [%1], 16;" :: "r"(sa), "l"(g));
}
#define CP_COMMIT() asm volatile("cp.async.commit_group;")
#define CP_WAITG(n) asm volatile("cp.async.wait_group %0;" :: "n"(n))

// ---------------- QKV projection: grid (128, 3) ----------------
__global__ __launch_bounds__(256, 1) void qkv_kernel(
    const float* __restrict__ x, const float* __restrict__ Wq,
    const float* __restrict__ Wk, const float* __restrict__ Wv)
{
    extern __shared__ float sm[];
    float* xs = sm;            // 128x132
    float* ws = sm + 128*132;  // 128x128
    const int tid = threadIdx.x, tx = tid & 15, ty = tid >> 4;
    const int tok0 = blockIdx.x * 128, w = blockIdx.y;
    const float* W = (w == 0) ? Wq : (w == 1) ? Wk : Wv;
    float* outp    = (w == 0) ? g_Q : (w == 1) ? g_K : g_V;

    for (int i = tid; i < 128*32; i += 256) {
        int r = i >> 5, c = (i & 31) << 2;
        *(float4*)&xs[r*132 + c] = *(const float4*)&x[(size_t)(tok0 + r)*DD + c];
        *(float4*)&ws[r*128 + c] = *(const float4*)&W[r*DD + c];
    }
    __syncthreads();
    float acc[8][8];
    #pragma unroll
    for (int i = 0; i < 8; i++)
        #pragma unroll
        for (int j = 0; j < 8; j++) acc[i][j] = 0.f;
    for (int kk = 0; kk < 128; kk++) {
        float xv[8], wv[8];
        #pragma unroll
        for (int i = 0; i < 8; i++) xv[i] = xs[(ty*8+i)*132 + kk];
        #pragma unroll
        for (int j = 0; j < 4; j++) {
            wv[j]   = ws[kk*128 + tx*4 + j];
            wv[4+j] = ws[kk*128 + 64 + tx*4 + j];
        }
        #pragma unroll
        for (int i = 0; i < 8; i++)
            #pragma unroll
            for (int j = 0; j < 8; j++) acc[i][j] += xv[i]*wv[j];
    }
    #pragma unroll
    for (int i = 0; i < 8; i++) {
        size_t tk = (size_t)(tok0 + ty*8 + i)*DD;
        *(float4*)&outp[tk + tx*4]      = make_float4(acc[i][0],acc[i][1],acc[i][2],acc[i][3]);
        *(float4*)&outp[tk + 64 + tx*4] = make_float4(acc[i][4],acc[i][5],acc[i][6],acc[i][7]);
    }
}

// ---------------- flash attention, tf32 mma.sync ----------------
// BM=128 q/CTA, BN=64 keys/tile. 8 warps = 4(M) x 2(N). grid (32,4) = 1 wave.
// smem floats: Qs[128*132]@0  Ks[2][64*132]@16896  Vs[64*132]@33792
//              Ps[128*68]@42240  Mred[2*128]@50944  Sred[2*128]@51200 (51456 total)
__global__ __launch_bounds__(256, 1) void attn_kernel(const float* __restrict__ conn)
{
    extern __shared__ float sm[];
    float* Qs = sm;
    float* Ks = sm + 16896;
    float* Vs = sm + 33792;
    float* Ps = sm + 42240;
    float* Mred = sm + 50944;
    float* Sred = sm + 51200;

    const int tid = threadIdx.x, lane = tid & 31, w = tid >> 5;
    const int g = lane >> 2, t = lane & 3;
    const int wm = w & 3, wn = w >> 2;
    const int b = blockIdx.y, q0 = blockIdx.x * 128;

    const float* Qg = g_Q + (size_t)b*AA*DD;
    const float* Kg = g_K + (size_t)b*AA*DD;
    const float* Vg = g_V + (size_t)b*AA*DD;

    // Q tile, pre-converted to tf32
    for (int i = tid; i < 128*32; i += 256) {
        int r = i >> 5, c = (i & 31) << 2;
        float4 v = *(const float4*)&Qg[(size_t)(q0 + r)*DD + c];
        uint4 u; u.x=f2tf32(v.x); u.y=f2tf32(v.y); u.z=f2tf32(v.z); u.w=f2tf32(v.w);
        *(uint4*)&Qs[r*132 + c] = u;
    }
    // prologue: K(0)
    for (int i = tid; i < 64*32; i += 256) {
        int r = i >> 5, c = (i & 31) << 2;
        cp16(&Ks[r*132 + c], &Kg[(size_t)r*DD + c]);
    }
    CP_COMMIT();

    float Oc[2][8][4];
    float mst[2][2], lst[2][2];
    #pragma unroll
    for (int mi = 0; mi < 2; mi++) {
        mst[mi][0] = -1e30f; mst[mi][1] = -1e30f;
        lst[mi][0] = 0.f;    lst[mi][1] = 0.f;
        #pragma unroll
        for (int nt = 0; nt < 8; nt++)
            #pragma unroll
            for (int j = 0; j < 4; j++) Oc[mi][nt][j] = 0.f;
    }
    const float inv_scale = 0.08838834764831845f;

    for (int kt = 0; kt < 64; kt++) {
        const int k0 = kt * 64;
        __syncthreads();                                   // Vs/Ps/K-buf free
        // V(kt)
        for (int i = tid; i < 64*32; i += 256) {
            int r = i >> 5, c = (i & 31) << 2;
            cp16(&Vs[r*132 + c], &Vg[(size_t)(k0 + r)*DD + c]);
        }
        CP_COMMIT();
        // K(kt+1)
        if (kt < 63) {
            const float* src = &Kg[(size_t)(k0 + 64)*DD];
            float* dst = &Ks[((kt+1)&1)*8448];
            for (int i = tid; i < 64*32; i += 256) {
                int r = i >> 5, c = (i & 31) << 2;
                cp16(&dst[r*132 + c], &src[(size_t)r*DD + c]);
            }
        }
        CP_COMMIT();
        // conn prefetch (fragment-aligned, 32B sectors)
        float2 cn[2][2][4];
        #pragma unroll
        for (int mi = 0; mi < 2; mi++)
            #pragma unroll
            for (int h = 0; h < 2; h++) {
                int r = q0 + 32*wm + 16*mi + 8*h + g;
                const float* cp_ = conn + ((size_t)b*AA + r)*AA + k0 + 32*wn + 2*t;
                #pragma unroll
                for (int nt = 0; nt < 4; nt++) cn[mi][h][nt] = *(const float2*)(cp_ + 8*nt);
            }
        CP_WAITG(2);         // K(kt) landed
        __syncthreads();
        const float* Kb = &Ks[(kt&1)*8448];

        // ---- S = Q . K^T ----
        float Sc[2][4][4];
        #pragma unroll
        for (int mi = 0; mi < 2; mi++)
            #pragma unroll
            for (int nt = 0; nt < 4; nt++)
                #pragma unroll
                for (int j = 0; j < 4; j++) Sc[mi][nt][j] = 0.f;
        #pragma unroll
        for (int ks = 0; ks < 16; ks++) {
            uint32_t a[2][4];
            #pragma unroll
            for (int mi = 0; mi < 2; mi++) {
                int base = (32*wm + 16*mi + g)*132 + 8*ks + t;
                a[mi][0] = __float_as_uint(Qs[base]);
                a[mi][1] = __float_as_uint(Qs[base + 8*132]);
                a[mi][2] = __float_as_uint(Qs[base + 4]);
                a[mi][3] = __float_as_uint(Qs[base + 8*132 + 4]);
            }
            #pragma unroll
            for (int nt = 0; nt < 4; nt++) {
                int kr = (32*wn + 8*nt + g)*132 + 8*ks + t;
                uint32_t b0 = f2tf32(Kb[kr]);
                uint32_t b1 = f2tf32(Kb[kr + 4]);
                mma_tf32(Sc[0][nt], a[0], b0, b1);
                mma_tf32(Sc[1][nt], a[1], b0, b1);
            }
        }
        // ---- scale + bias ----
        #pragma unroll
        for (int mi = 0; mi < 2; mi++)
            #pragma unroll
            for (int nt = 0; nt < 4; nt++) {
                Sc[mi][nt][0] = Sc[mi][nt][0]*inv_scale + cn[mi][0][nt].x;
                Sc[mi][nt][1] = Sc[mi][nt][1]*inv_scale + cn[mi][0][nt].y;
                Sc[mi][nt][2] = Sc[mi][nt][2]*inv_scale + cn[mi][1][nt].x;
                Sc[mi][nt][3] = Sc[mi][nt][3]*inv_scale + cn[mi][1][nt].y;
            }
        // ---- row max (quad -> cross-warp) ----
        float mx[2][2];
        #pragma unroll
        for (int mi = 0; mi < 2; mi++)
            #pragma unroll
            for (int h = 0; h < 2; h++) {
                float v = fmaxf(Sc[mi][0][2*h], Sc[mi][0][2*h+1]);
                #pragma unroll
                for (int nt = 1; nt < 4; nt++)
                    v = fmaxf(v, fmaxf(Sc[mi][nt][2*h], Sc[mi][nt][2*h+1]));
                v = fmaxf(v, __shfl_xor_sync(0xffffffffu, v, 1));
                v = fmaxf(v, __shfl_xor_sync(0xffffffffu, v, 2));
                mx[mi][h] = v;
            }
        if (t == 0) {
            #pragma unroll
            for (int mi = 0; mi < 2; mi++)
                #pragma unroll
                for (int h = 0; h < 2; h++)
                    Mred[wn*128 + 32*wm + 16*mi + 8*h + g] = mx[mi][h];
        }
        __syncthreads();
        float mnew[2][2], scf[2][2];
        #pragma unroll
        for (int mi = 0; mi < 2; mi++)
            #pragma unroll
            for (int h = 0; h < 2; h++) {
                int r = 32*wm + 16*mi + 8*h + g;
                float v = fmaxf(Mred[r], Mred[128 + r]);
                float mn = fmaxf(mst[mi][h], v);
                scf[mi][h] = __expf(mst[mi][h] - mn);
                mst[mi][h] = mn;
                mnew[mi][h] = mn;
            }
        // ---- exp, store P (tf32), partial sums ----
        float rs[2][2] = {{0.f,0.f},{0.f,0.f}};
        #pragma unroll
        for (int mi = 0; mi < 2; mi++)
            #pragma unroll
            for (int nt = 0; nt < 4; nt++) {
                float p0 = __expf(Sc[mi][nt][0] - mnew[mi][0]);
                float p1 = __expf(Sc[mi][nt][1] - mnew[mi][0]);
                float p2 = __expf(Sc[mi][nt][2] - mnew[mi][1]);
                float p3 = __expf(Sc[mi][nt][3] - mnew[mi][1]);
                rs[mi][0] += p0 + p1;
                rs[mi][1] += p2 + p3;
                int base = (32*wm + 16*mi + g)*68 + 32*wn + 8*nt + 2*t;
                float2 v0, v1;
                v0.x = __uint_as_float(f2tf32(p0)); v0.y = __uint_as_float(f2tf32(p1));
                v1.x = __uint_as_float(f2tf32(p2)); v1.y = __uint_as_float(f2tf32(p3));
                *(float2*)&Ps[base]          = v0;
                *(float2*)&Ps[base + 8*68]   = v1;
            }
        #pragma unroll
        for (int mi = 0; mi < 2; mi++)
            #pragma unroll
            for (int h = 0; h < 2; h++) {
                float v = rs[mi][h];
                v += __shfl_xor_sync(0xffffffffu, v, 1);
                v += __shfl_xor_sync(0xffffffffu, v, 2);
                rs[mi][h] = v;
            }
        if (t == 0) {
            #pragma unroll
            for (int mi = 0; mi < 2; mi++)
                #pragma unroll
                for (int h = 0; h < 2; h++)
                    Sred[wn*128 + 32*wm + 16*mi + 8*h + g] = rs[mi][h];
        }
        CP_WAITG(1);         // V(kt) landed
        __syncthreads();     // Ps + Sred + Vs visible
        #pragma unroll
        for (int mi = 0; mi < 2; mi++)
            #pragma unroll
            for (int h = 0; h < 2; h++) {
                int r = 32*wm + 16*mi + 8*h + g;
                lst[mi][h] = lst[mi][h]*scf[mi][h] + Sred[r] + Sred[128 + r];
            }
        // rescale O
        #pragma unroll
        for (int mi = 0; mi < 2; mi++)
            #pragma unroll
            for (int nt = 0; nt < 8; nt++) {
                Oc[mi][nt][0] *= scf[mi][0]; Oc[mi][nt][1] *= scf[mi][0];
                Oc[mi][nt][2] *= scf[mi][1]; Oc[mi][nt][3] *= scf[mi][1];
            }
        // ---- O += P . V ----
        #pragma unroll
        for (int ks = 0; ks < 8; ks++) {
            uint32_t a[2][4];
            #pragma unroll
            for (int mi = 0; mi < 2; mi++) {
                int base = (32*wm + 16*mi + g)*68 + 8*ks + t;
                a[mi][0] = __float_as_uint(Ps[base]);
                a[mi][1] = __float_as_uint(Ps[base + 8*68]);
                a[mi][2] = __float_as_uint(Ps[base + 4]);
                a[mi][3] = __float_as_uint(Ps[base + 8*68 + 4]);
            }
            #pragma unroll
            for (int nt = 0; nt < 8; nt++) {
                int vb = (8*ks + t)*132 + 64*wn + 8*nt + g;
                uint32_t b0 = f2tf32(Vs[vb]);
                uint32_t b1 = f2tf32(Vs[vb + 4*132]);
                mma_tf32(Oc[0][nt], a[0], b0, b1);
                mma_tf32(Oc[1][nt], a[1], b0, b1);
            }
        }
    }
    // epilogue: normalize + store H
    float* Hg = g_H + (size_t)b*AA*DD;
    float inv[2][2];
    #pragma unroll
    for (int mi = 0; mi < 2; mi++) {
        inv[mi][0] = 1.0f / lst[mi][0];
        inv[mi][1] = 1.0f / lst[mi][1];
    }
    #pragma unroll
    for (int mi = 0; mi < 2; mi++)
        #pragma unroll
        for (int nt = 0; nt < 8; nt++) {
            int r0 = q0 + 32*wm + 16*mi + g;
            int col = 64*wn + 8*nt + 2*t;
            float2 v0, v1;
            v0.x = Oc[mi][nt][0]*inv[mi][0]; v0.y = Oc[mi][nt][1]*inv[mi][0];
            v1.x = Oc[mi][nt][2]*inv[mi][1]; v1.y = Oc[mi][nt][3]*inv[mi][1];
            *(float2*)&Hg[(size_t)r0*DD + col]       = v0;
            *(float2*)&Hg[(size_t)(r0+8)*DD + col]   = v1;
        }
}

// ---------------- swish -> W1 -> swish -> W2 -> LayerNorm ----------------
__global__ __launch_bounds__(256, 1) void mlp_kernel(
    const float* __restrict__ W1, const float* __restrict__ b1,
    const float* __restrict__ W2, const float* __restrict__ b2,
    const float* __restrict__ gamma, const float* __restrict__ beta,
    float* __restrict__ out)
{
    extern __shared__ float sm[];
    float* hs  = sm;
    float* hs2 = hs + 128*132;
    float* ws  = hs2 + 128*132;
    const int tid = threadIdx.x, tx = tid & 15, ty = tid >> 4;
    const int tok0 = blockIdx.x * 128;

    for (int i = tid; i < 128*32; i += 256) {
        int r = i >> 5, c = (i & 31) << 2;
        float4 v = *(const float4*)&g_H[(size_t)(tok0 + r)*DD + c];
        v.x = swishf(v.x); v.y = swishf(v.y); v.z = swishf(v.z); v.w = swishf(v.w);
        *(float4*)&hs[r*132 + c] = v;
        *(float4*)&ws[r*128 + c] = *(const float4*)&W1[r*DD + c];
    }
    __syncthreads();

    float acc[8][8];
    #pragma unroll
    for (int j = 0; j < 4; j++) {
        float bA = b1[tx*4 + j], bB = b1[64 + tx*4 + j];
        #pragma unroll
        for (int i = 0; i < 8; i++) { acc[i][j] = bA; acc[i][4+j] = bB; }
    }
    for (int kk = 0; kk < 128; kk++) {
        float xv[8], wv[8];
        #pragma unroll
        for (int i = 0; i < 8; i++) xv[i] = hs[(ty*8+i)*132 + kk];
        #pragma unroll
        for (int j = 0; j < 4; j++) {
            wv[j]   = ws[kk*128 + tx*4 + j];
            wv[4+j] = ws[kk*128 + 64 + tx*4 + j];
        }
        #pragma unroll
        for (int i = 0; i < 8; i++)
            #pragma unroll
            for (int j = 0; j < 8; j++) acc[i][j] += xv[i]*wv[j];
    }
    __syncthreads();

    #pragma unroll
    for (int i = 0; i < 8; i++) {
        *(float4*)&hs2[(ty*8+i)*132 + tx*4] =
            make_float4(swishf(acc[i][0]),swishf(acc[i][1]),swishf(acc[i][2]),swishf(acc[i][3]));
        *(float4*)&hs2[(ty*8+i)*132 + 64 + tx*4] =
            make_float4(swishf(acc[i][4]),swishf(acc[i][5]),swishf(acc[i][6]),swishf(acc[i][7]));
    }
    for (int i = tid; i < 128*32; i += 256) {
        int r = i >> 5, c = (i & 31) << 2;
        *(float4*)&ws[r*128 + c] = *(const float4*)&W2[r*DD + c];
    }
    __syncthreads();

    #pragma unroll
    for (int j = 0; j < 4; j++) {
        float bA = b2[tx*4 + j], bB = b2[64 + tx*4 + j];
        #pragma unroll
        for (int i = 0; i < 8; i++) { acc[i][j] = bA; acc[i][4+j] = bB; }
    }
    for (int kk = 0; kk < 128; kk++) {
        float xv[8], wv[8];
        #pragma unroll
        for (int i = 0; i < 8; i++) xv[i] = hs2[(ty*8+i)*132 + kk];
        #pragma unroll
        for (int j = 0; j < 4; j++) {
            wv[j]   = ws[kk*128 + tx*4 + j];
            wv[4+j] = ws[kk*128 + 64 + tx*4 + j];
        }
        #pragma unroll
        for (int i = 0; i < 8; i++)
            #pragma unroll
            for (int j = 0; j < 8; j++) acc[i][j] += xv[i]*wv[j];
    }

    float gm[8], bt[8];
    #pragma unroll
    for (int j = 0; j < 4; j++) {
        gm[j]   = gamma[tx*4+j]; gm[4+j] = gamma[64+tx*4+j];
        bt[j]   = beta[tx*4+j];  bt[4+j] = beta[64+tx*4+j];
    }
    #pragma unroll
    for (int i = 0; i < 8; i++) {
        float s1 = 0.f, s2 = 0.f;
        #pragma unroll
        for (int j = 0; j < 8; j++) { s1 += acc[i][j]; s2 += acc[i][j]*acc[i][j]; }
        #pragma unroll
        for (int o = 8; o; o >>= 1) {
            s1 += __shfl_xor_sync(0xffffffffu, s1, o);
            s2 += __shfl_xor_sync(0xffffffffu, s2, o);
        }
        float mu  = s1 * (1.0f/128.0f);
        float var = s2 * (1.0f/128.0f) - mu*mu;
        float rstd = rsqrtf(var + 1e-5f);
        size_t base = (size_t)(tok0 + ty*8 + i)*DD;
        float4 o0, o1;
        o0.x = (acc[i][0]-mu)*rstd*gm[0] + bt[0];
        o0.y = (acc[i][1]-mu)*rstd*gm[1] + bt[1];
        o0.z = (acc[i][2]-mu)*rstd*gm[2] + bt[2];
        o0.w = (acc[i][3]-mu)*rstd*gm[3] + bt[3];
        o1.x = (acc[i][4]-mu)*rstd*gm[4] + bt[4];
        o1.y = (acc[i][5]-mu)*rstd*gm[5] + bt[5];
        o1.z = (acc[i][6]-mu)*rstd*gm[6] + bt[6];
        o1.w = (acc[i][7]-mu)*rstd*gm[7] + bt[7];
        *(float4*)&out[base + tx*4]      = o0;
        *(float4*)&out[base + 64 + tx*4] = o1;
    }
}

extern "C" void kernel_launch(void* const* d_in, const int* in_sizes, int n_in,
                              void* d_out, int out_size)
{
    const float* x     = (const float*)d_in[0];
    const float* conn  = (const float*)d_in[1];
    const float* Wq    = (const float*)d_in[2];
    const float* Wk    = (const float*)d_in[3];
    const float* Wv    = (const float*)d_in[4];
    const float* W1    = (const float*)d_in[5];
    const float* b1    = (const float*)d_in[6];
    const float* W2    = (const float*)d_in[7];
    const float* b2    = (const float*)d_in[8];
    const float* gamma = (const float*)d_in[9];
    const float* beta  = (const float*)d_in[10];
    float* out = (float*)d_out;

    const size_t smem_qkv  = (size_t)(128*132 + 128*128) * sizeof(float);   // 133120
    const size_t smem_attn = (size_t)51456 * sizeof(float);                 // 205824
    const size_t smem_mlp  = (size_t)(128*132*2 + 128*128) * sizeof(float); // 200704

    cudaFuncSetAttribute(qkv_kernel,  cudaFuncAttributeMaxDynamicSharedMemorySize, (int)smem_qkv);
    cudaFuncSetAttribute(attn_kernel, cudaFuncAttributeMaxDynamicSharedMemorySize, (int)smem_attn);
    cudaFuncSetAttribute(mlp_kernel,  cudaFuncAttributeMaxDynamicSharedMemorySize, (int)smem_mlp);

    qkv_kernel<<<dim3(128, 3), 256, smem_qkv>>>(x, Wq, Wk, Wv);
    attn_kernel<<<dim3(32, 4), 256, smem_attn>>>(conn);
    mlp_kernel<<<128, 256, smem_mlp>>>(W1, b1, W2, b2, gamma, beta, out);
}